// round 2
// baseline (speedup 1.0000x reference)
#include <cuda_runtime.h>
#include <cstdint>

#define NIMG   4096
#define TSTEPS 128
#define BATCH  32
#define HID    128

// Scratch (device globals; no allocation allowed)
__device__ float g_z1[(size_t)NIMG * 4 * 400 * 8];    // conv1 out [n][g=oc/8][pix400][oc%8]
__device__ float g_z2[(size_t)NIMG * 4 * 81 * 16];    // conv2 out [n][cc=oc/16][pix81][oc%16]
__device__ float g_z3[(size_t)NIMG * 3136];           // conv3 out, NCHW flatten
__device__ float g_hidden[(size_t)NIMG * 512];        // FC out
__device__ float g_gates[(size_t)NIMG * 512];         // x-proj of gates (+both biases)
__device__ float g_hs[(size_t)NIMG * HID];            // per-step hidden outputs

// ---------------------------------------------------------------------------
// conv1: 1x84x84 -> 32x20x20, k=8, s=4. One block per image.
// 200 pixel-pairs x 2 oc-groups(16) = 400 active threads, 32 accums each.
// ---------------------------------------------------------------------------
__global__ __launch_bounds__(512) void conv1_kernel(const float* __restrict__ x,
                                                    const float* __restrict__ W1,
                                                    const float* __restrict__ b1) {
    __shared__ float img[84 * 84];
    __shared__ float ws[64 * 32];   // [k][oc]
    __shared__ float bs[32];
    const int n = blockIdx.x;
    const int tid = threadIdx.x;
    const float* xin = x + (size_t)n * 7056;
    for (int i = tid; i < 7056; i += 512) img[i] = xin[i] * (1.0f / 255.0f);
    for (int i = tid; i < 2048; i += 512) {
        int k = i >> 5, oc = i & 31;
        ws[i] = W1[oc * 64 + k];
    }
    if (tid < 32) bs[tid] = b1[tid];
    __syncthreads();

    if (tid < 400) {
        const int ocg = tid & 1;           // oc base = ocg*16
        const int pp  = tid >> 1;          // pixel pair 0..199
        const int p0  = pp * 2;
        const int oy  = p0 / 20, ox0 = p0 % 20;
        const int iy  = oy * 4,  ix  = ox0 * 4;

        float acc0[16], acc1[16];
#pragma unroll
        for (int o = 0; o < 16; o++) { acc0[o] = 0.f; acc1[o] = 0.f; }

#pragma unroll
        for (int ky = 0; ky < 8; ky++) {
            const float* ip = &img[(iy + ky) * 84 + ix];
            const float4 q0 = *(const float4*)(ip);
            const float4 q1 = *(const float4*)(ip + 4);
            const float4 q2 = *(const float4*)(ip + 8);
            float v[12];
            v[0]=q0.x; v[1]=q0.y; v[2]=q0.z; v[3]=q0.w;
            v[4]=q1.x; v[5]=q1.y; v[6]=q1.z; v[7]=q1.w;
            v[8]=q2.x; v[9]=q2.y; v[10]=q2.z; v[11]=q2.w;
#pragma unroll
            for (int kx = 0; kx < 8; kx++) {
                const float vv0 = v[kx];
                const float vv1 = v[kx + 4];
                const float* wp = &ws[(ky * 8 + kx) * 32 + ocg * 16];
                const float4 w0 = *(const float4*)(wp);
                const float4 w1 = *(const float4*)(wp + 4);
                const float4 w2 = *(const float4*)(wp + 8);
                const float4 w3 = *(const float4*)(wp + 12);
                const float wv[16] = {w0.x,w0.y,w0.z,w0.w, w1.x,w1.y,w1.z,w1.w,
                                      w2.x,w2.y,w2.z,w2.w, w3.x,w3.y,w3.z,w3.w};
#pragma unroll
                for (int o = 0; o < 16; o++) {
                    acc0[o] += vv0 * wv[o];
                    acc1[o] += vv1 * wv[o];
                }
            }
        }
        float* zp = g_z1 + (size_t)n * 12800;
#pragma unroll
        for (int o = 0; o < 16; o++) {
            const int oc = ocg * 16 + o;
            const int g = oc >> 3, l = oc & 7;
            const float r0 = fmaxf(acc0[o] + bs[oc], 0.f);
            const float r1 = fmaxf(acc1[o] + bs[oc], 0.f);
            zp[(g * 400 + p0) * 8 + l]     = r0;
            zp[(g * 400 + p0 + 1) * 8 + l] = r1;
        }
    }
}

// ---------------------------------------------------------------------------
// conv2: 32x20x20 -> 64x9x9, k=4, s=2. One block per image.
// 27 pixel-triples x 8 oc-groups = 216 active threads, 24 accums each.
// ---------------------------------------------------------------------------
__global__ __launch_bounds__(256) void conv2_kernel(const float* __restrict__ W2,
                                                    const float* __restrict__ b2) {
    __shared__ float in_s[400 * 8];     // [pix][ic8]
    __shared__ float w_s[64 * 16 * 8];  // [oc][k16][ic8]
    const int n = blockIdx.x;
    const int tid = threadIdx.x;
    const int ocg  = tid & 7;
    const int trip = tid >> 3;
    const bool active = (trip < 27);

    int py[3], px[3];
#pragma unroll
    for (int i = 0; i < 3; i++) {
        int p = trip * 3 + i;
        if (p > 80) p = 80;
        py[i] = p / 9; px[i] = p % 9;
    }

    float acc[3][8];
#pragma unroll
    for (int i = 0; i < 3; i++)
#pragma unroll
        for (int o = 0; o < 8; o++) acc[i][o] = 0.f;

    for (int c = 0; c < 4; c++) {
        __syncthreads();
        const float* zin = g_z1 + ((size_t)n * 4 + c) * 3200;
        for (int i = tid; i < 3200; i += 256) in_s[i] = zin[i];
        for (int i = tid; i < 8192; i += 256) {
            int oc = i >> 7, r = i & 127, k = r >> 3, icl = r & 7;
            w_s[i] = W2[oc * 512 + (c * 8 + icl) * 16 + k];
        }
        __syncthreads();
        if (active) {
#pragma unroll
            for (int k = 0; k < 16; k++) {
                const int ky = k >> 2, kx = k & 3;
                float4 a[3][2];
#pragma unroll
                for (int i = 0; i < 3; i++) {
                    const int ib = ((py[i] * 2 + ky) * 20 + px[i] * 2 + kx) * 8;
                    a[i][0] = *(const float4*)&in_s[ib];
                    a[i][1] = *(const float4*)&in_s[ib + 4];
                }
#pragma unroll
                for (int o = 0; o < 8; o++) {
                    const float4* wp = (const float4*)&w_s[((ocg * 8 + o) * 16 + k) * 8];
                    const float4 w0 = wp[0], w1 = wp[1];
#pragma unroll
                    for (int i = 0; i < 3; i++) {
                        acc[i][o] += a[i][0].x * w0.x + a[i][0].y * w0.y +
                                     a[i][0].z * w0.z + a[i][0].w * w0.w +
                                     a[i][1].x * w1.x + a[i][1].y * w1.y +
                                     a[i][1].z * w1.z + a[i][1].w * w1.w;
                    }
                }
            }
        }
    }
    if (active) {
#pragma unroll
        for (int i = 0; i < 3; i++) {
            const int p = trip * 3 + i;
#pragma unroll
            for (int o = 0; o < 8; o++) {
                const int oc = ocg * 8 + o;
                const float r = fmaxf(acc[i][o] + b2[oc], 0.f);
                g_z2[(((size_t)n * 4 + (oc >> 4)) * 81 + p) * 16 + (oc & 15)] = r;
            }
        }
    }
}

// ---------------------------------------------------------------------------
// conv3: 64x9x9 -> 64x7x7, k=3, s=1. TWO images per block.
// per image: 7 rows x 16 oc-groups(4) = 112 threads; 7px x 4oc = 28 accums.
// ---------------------------------------------------------------------------
__global__ __launch_bounds__(256) void conv3_kernel(const float* __restrict__ W3,
                                                    const float* __restrict__ b3) {
    __shared__ float in_s[2 * 1296];    // [img][pix81][ic16]
    __shared__ float w_s[64 * 9 * 16];  // [oc][k9][ic16]
    const int n0 = blockIdx.x * 2;
    const int tid = threadIdx.x;
    const int img = tid / 112;
    const int r   = tid % 112;
    const int ty  = r / 16;     // output row 0..6
    const int og  = r % 16;     // oc group (4 oc each)
    const bool active = (tid < 224);

    float acc[7][4];
#pragma unroll
    for (int i = 0; i < 7; i++)
#pragma unroll
        for (int o = 0; o < 4; o++) acc[i][o] = 0.f;

    for (int cc = 0; cc < 4; cc++) {
        __syncthreads();
        for (int i = tid; i < 2592; i += 256) {
            const int im = i / 1296, idx = i % 1296;
            in_s[i] = g_z2[(((size_t)(n0 + im) * 4 + cc) * 1296) + idx];
        }
        for (int i = tid; i < 9216; i += 256) {
            const int oc = i / 144, r2 = i % 144, k = r2 >> 4, icl = r2 & 15;
            w_s[i] = W3[oc * 576 + (cc * 16 + icl) * 9 + k];
        }
        __syncthreads();
        if (active) {
            const float* inb = &in_s[img * 1296];
#pragma unroll
            for (int k = 0; k < 9; k++) {
                const int ky = k / 3, kx = k % 3;
#pragma unroll
                for (int icv = 0; icv < 4; icv++) {
                    float4 av[7];
#pragma unroll
                    for (int ox = 0; ox < 7; ox++)
                        av[ox] = *(const float4*)&inb[((ty + ky) * 9 + kx + ox) * 16 + icv * 4];
#pragma unroll
                    for (int o = 0; o < 4; o++) {
                        const float4 w = *(const float4*)&w_s[((og * 4 + o) * 9 + k) * 16 + icv * 4];
#pragma unroll
                        for (int ox = 0; ox < 7; ox++) {
                            acc[ox][o] += av[ox].x * w.x + av[ox].y * w.y +
                                          av[ox].z * w.z + av[ox].w * w.w;
                        }
                    }
                }
            }
        }
    }
    if (active) {
#pragma unroll
        for (int o = 0; o < 4; o++) {
            const int oc = og * 4 + o;
            const float bb = b3[oc];
            float* zp = &g_z3[(size_t)(n0 + img) * 3136 + oc * 49 + ty * 7];
#pragma unroll
            for (int ox = 0; ox < 7; ox++)
                zp[ox] = fmaxf(acc[ox][o] + bb, 0.f);
        }
    }
}

// ---------------------------------------------------------------------------
// GEMM: C[M,N] = A[M,K] * B[N,K]^T + bias(+bias2), optional relu.
// BM=BN=128, BK=8, 256 threads, 8x8 microtile. N (ldc) = 512.
// ---------------------------------------------------------------------------
__device__ __forceinline__ void gemm128(const float* __restrict__ A,
                                        const float* __restrict__ B,
                                        float* __restrict__ C, int K,
                                        const float* __restrict__ bias1,
                                        const float* __restrict__ bias2,
                                        bool relu) {
    __shared__ float As[8][132];
    __shared__ float Bs[8][132];
    const int tid = threadIdx.x;
    const int m0 = blockIdx.y * 128, n0 = blockIdx.x * 128;
    const int lr = tid >> 1, lk = (tid & 1) * 4;
    const int tx = tid & 15, ty = tid >> 4;

    float acc[8][8];
#pragma unroll
    for (int i = 0; i < 8; i++)
#pragma unroll
        for (int j = 0; j < 8; j++) acc[i][j] = 0.f;

    const float* Ap = A + (size_t)(m0 + lr) * K + lk;
    const float* Bp = B + (size_t)(n0 + lr) * K + lk;

    for (int k0 = 0; k0 < K; k0 += 8) {
        const float4 av = *(const float4*)(Ap + k0);
        const float4 bv = *(const float4*)(Bp + k0);
        As[lk + 0][lr] = av.x; As[lk + 1][lr] = av.y;
        As[lk + 2][lr] = av.z; As[lk + 3][lr] = av.w;
        Bs[lk + 0][lr] = bv.x; Bs[lk + 1][lr] = bv.y;
        Bs[lk + 2][lr] = bv.z; Bs[lk + 3][lr] = bv.w;
        __syncthreads();
#pragma unroll
        for (int kk = 0; kk < 8; kk++) {
            const float4 a0 = *(const float4*)&As[kk][ty * 4];
            const float4 a1 = *(const float4*)&As[kk][ty * 4 + 64];
            const float4 b0 = *(const float4*)&Bs[kk][tx * 4];
            const float4 b1 = *(const float4*)&Bs[kk][tx * 4 + 64];
            const float am[8] = {a0.x,a0.y,a0.z,a0.w, a1.x,a1.y,a1.z,a1.w};
            const float bn[8] = {b0.x,b0.y,b0.z,b0.w, b1.x,b1.y,b1.z,b1.w};
#pragma unroll
            for (int i = 0; i < 8; i++)
#pragma unroll
                for (int j = 0; j < 8; j++)
                    acc[i][j] += am[i] * bn[j];
        }
        __syncthreads();
    }

    float bb[8];
#pragma unroll
    for (int j = 0; j < 8; j++) {
        const int nn = n0 + ((j < 4) ? (tx * 4 + j) : (tx * 4 + 60 + j));
        bb[j] = bias1[nn] + (bias2 ? bias2[nn] : 0.f);
    }
#pragma unroll
    for (int i = 0; i < 8; i++) {
        const int mm = m0 + ((i < 4) ? (ty * 4 + i) : (ty * 4 + 60 + i));
        float v[8];
#pragma unroll
        for (int j = 0; j < 8; j++) {
            v[j] = acc[i][j] + bb[j];
            if (relu) v[j] = fmaxf(v[j], 0.f);
        }
        float4 o0 = {v[0], v[1], v[2], v[3]};
        float4 o1 = {v[4], v[5], v[6], v[7]};
        *(float4*)&C[(size_t)mm * 512 + n0 + tx * 4]      = o0;
        *(float4*)&C[(size_t)mm * 512 + n0 + tx * 4 + 64] = o1;
    }
}

__global__ __launch_bounds__(256) void fc_gemm_kernel(const float* __restrict__ Wfc,
                                                      const float* __restrict__ bfc) {
    gemm128(g_z3, Wfc, g_hidden, 3136, bfc, nullptr, true);
}
__global__ __launch_bounds__(256) void gates_gemm_kernel(const float* __restrict__ W_ih,
                                                         const float* __restrict__ b_ih,
                                                         const float* __restrict__ b_hh) {
    gemm128(g_hidden, W_ih, g_gates, 512, b_ih, b_hh, false);
}

// ---------------------------------------------------------------------------
// LSTM: batch elements are independent -> one block per batch element,
// NO grid barrier. 512 threads: thread j computes gate row j each step.
// W_hh (256KB) streamed from L1/L2 each step; h,c live in smem.
// ---------------------------------------------------------------------------
__device__ __forceinline__ float sigmoidf_(float v) {
    return 1.0f / (1.0f + __expf(-v));
}

__global__ __launch_bounds__(512) void lstm_kernel(const float* __restrict__ done,
                                                   const float* __restrict__ W_hh,
                                                   const float* __restrict__ h0,
                                                   const float* __restrict__ c0,
                                                   float* __restrict__ out) {
    __shared__ float hs[HID];
    __shared__ float cs[HID];
    __shared__ float hm[HID];
    __shared__ float gg[512];
    const int b = blockIdx.x;
    const int tid = threadIdx.x;

    if (tid < HID) {
        hs[tid] = h0[b * HID + tid];
        cs[tid] = c0[b * HID + tid];
    }
    __syncthreads();

    const float4* wp = (const float4*)(W_hh + tid * HID);  // row j, 32 float4

    for (int t = 0; t < TSTEPS; t++) {
        const float mask = 1.0f - done[t * BATCH + b];
        if (tid < HID) hm[tid] = hs[tid] * mask;
        __syncthreads();

        const float4* hp = (const float4*)hm;
        float a0 = 0.f, a1 = 0.f, a2 = 0.f, a3 = 0.f;
#pragma unroll
        for (int q = 0; q < 32; q += 4) {
            const float4 w0 = wp[q + 0], h0v = hp[q + 0];
            const float4 w1 = wp[q + 1], h1v = hp[q + 1];
            const float4 w2 = wp[q + 2], h2v = hp[q + 2];
            const float4 w3 = wp[q + 3], h3v = hp[q + 3];
            a0 += w0.x*h0v.x + w0.y*h0v.y + w0.z*h0v.z + w0.w*h0v.w;
            a1 += w1.x*h1v.x + w1.y*h1v.y + w1.z*h1v.z + w1.w*h1v.w;
            a2 += w2.x*h2v.x + w2.y*h2v.y + w2.z*h2v.z + w2.w*h2v.w;
            a3 += w3.x*h3v.x + w3.y*h3v.y + w3.z*h3v.z + w3.w*h3v.w;
        }
        gg[tid] = (a0 + a1) + (a2 + a3) + g_gates[(size_t)(t * BATCH + b) * 512 + tid];
        __syncthreads();

        if (tid < HID) {
            const float gi = gg[tid];
            const float gf = gg[tid + 128];
            const float gc = gg[tid + 256];
            const float go = gg[tid + 384];
            float c = cs[tid] * mask;
            c = sigmoidf_(gf) * c + sigmoidf_(gi) * tanhf(gc);
            const float h = sigmoidf_(go) * tanhf(c);
            cs[tid] = c;
            hs[tid] = h;
            g_hs[(size_t)(t * BATCH + b) * HID + tid] = h;
            if (t == TSTEPS - 1) {
                out[28672 + b * HID + tid] = h;
                out[32768 + b * HID + tid] = c;
            }
        }
        __syncthreads();
    }
}

// ---------------------------------------------------------------------------
// Heads: logits (4096x6) and value (4096x1) from g_hs.
// ---------------------------------------------------------------------------
__global__ __launch_bounds__(256) void heads_kernel(const float* __restrict__ Wa,
                                                    const float* __restrict__ ba,
                                                    const float* __restrict__ Wc,
                                                    const float* __restrict__ bc,
                                                    float* __restrict__ out) {
    __shared__ float was[6 * 128];
    __shared__ float wcs[128];
    __shared__ float bas[6];
    __shared__ float bcs;
    const int tid = threadIdx.x;
    for (int i = tid; i < 768; i += 256) was[i] = Wa[i];
    if (tid < 128) wcs[tid] = Wc[tid];
    if (tid < 6) bas[tid] = ba[tid];
    if (tid == 0) bcs = bc[0];
    __syncthreads();

    const int row = blockIdx.x * 256 + tid;
    const float* hp = &g_hs[(size_t)row * 128];
    float acc[6] = {0.f, 0.f, 0.f, 0.f, 0.f, 0.f};
    float accv = 0.f;
    for (int k = 0; k < 128; k += 4) {
        const float4 h4 = *(const float4*)&hp[k];
#pragma unroll
        for (int a = 0; a < 6; a++) {
            const float4 w4 = *(const float4*)&was[a * 128 + k];
            acc[a] += h4.x * w4.x + h4.y * w4.y + h4.z * w4.z + h4.w * w4.w;
        }
        const float4 wc4 = *(const float4*)&wcs[k];
        accv += h4.x * wc4.x + h4.y * wc4.y + h4.z * wc4.z + h4.w * wc4.w;
    }
#pragma unroll
    for (int a = 0; a < 6; a++) out[row * 6 + a] = acc[a] + bas[a];
    out[24576 + row] = accv + bcs;
}

// ---------------------------------------------------------------------------
// Launch
// ---------------------------------------------------------------------------
extern "C" void kernel_launch(void* const* d_in, const int* in_sizes, int n_in,
                              void* d_out, int out_size) {
    const float* x    = (const float*)d_in[0];
    const float* done = (const float*)d_in[1];
    const float* h0   = (const float*)d_in[2];
    const float* c0   = (const float*)d_in[3];
    const float* W1   = (const float*)d_in[4];
    const float* b1   = (const float*)d_in[5];
    const float* W2   = (const float*)d_in[6];
    const float* b2   = (const float*)d_in[7];
    const float* W3   = (const float*)d_in[8];
    const float* b3   = (const float*)d_in[9];
    const float* Wfc  = (const float*)d_in[10];
    const float* bfc  = (const float*)d_in[11];
    const float* W_ih = (const float*)d_in[12];
    const float* W_hh = (const float*)d_in[13];
    const float* b_ih = (const float*)d_in[14];
    const float* b_hh = (const float*)d_in[15];
    const float* Wa   = (const float*)d_in[16];
    const float* ba   = (const float*)d_in[17];
    const float* Wc   = (const float*)d_in[18];
    const float* bc   = (const float*)d_in[19];
    float* out = (float*)d_out;

    conv1_kernel<<<NIMG, 512>>>(x, W1, b1);
    conv2_kernel<<<NIMG, 256>>>(W2, b2);
    conv3_kernel<<<NIMG / 2, 256>>>(W3, b3);
    fc_gemm_kernel<<<dim3(4, 32), 256>>>(Wfc, bfc);
    gates_gemm_kernel<<<dim3(4, 32), 256>>>(W_ih, b_ih, b_hh);
    lstm_kernel<<<BATCH, 512>>>(done, W_hh, h0, c0, out);
    heads_kernel<<<16, 256>>>(Wa, ba, Wc, bc, out);
}

// round 4
// speedup vs baseline: 1.1438x; 1.1438x over previous
#include <cuda_runtime.h>
#include <cstdint>

#define NIMG   4096
#define TSTEPS 128
#define BATCH  32
#define HID    128

// Scratch (device globals; no allocation allowed)
__device__ float g_z1[(size_t)NIMG * 4 * 400 * 8];    // conv1 out [n][g=oc/8][pix400][oc%8]
__device__ float g_z2[(size_t)NIMG * 4 * 81 * 16];    // conv2 out [n][cc=oc/16][pix81][oc%16]
__device__ float g_z3[(size_t)NIMG * 3136];           // conv3 out, NCHW flatten
__device__ float g_hidden[(size_t)NIMG * 512];        // FC out
__device__ float g_gates[(size_t)NIMG * 512];         // x-proj of gates (+both biases)
__device__ float g_hs[(size_t)NIMG * HID];            // per-step hidden outputs
__device__ float g_whhT[HID * 512];                   // W_hh transposed: [k][row j]

// ---------------------------------------------------------------------------
// conv1: 1x84x84 -> 32x20x20, k=8, s=4. One block per image. (static smem OK)
// ---------------------------------------------------------------------------
__global__ __launch_bounds__(512) void conv1_kernel(const float* __restrict__ x,
                                                    const float* __restrict__ W1,
                                                    const float* __restrict__ b1) {
    __shared__ float img[84 * 84];
    __shared__ float ws[64 * 32];   // [k][oc]
    __shared__ float bs[32];
    const int n = blockIdx.x;
    const int tid = threadIdx.x;
    const float* xin = x + (size_t)n * 7056;
    for (int i = tid; i < 7056; i += 512) img[i] = xin[i] * (1.0f / 255.0f);
    for (int i = tid; i < 2048; i += 512) {
        int k = i >> 5, oc = i & 31;
        ws[i] = W1[oc * 64 + k];
    }
    if (tid < 32) bs[tid] = b1[tid];
    __syncthreads();

    if (tid < 400) {
        const int ocg = tid & 1;           // oc base = ocg*16
        const int pp  = tid >> 1;          // pixel pair 0..199
        const int p0  = pp * 2;
        const int oy  = p0 / 20, ox0 = p0 % 20;
        const int iy  = oy * 4,  ix  = ox0 * 4;

        float acc0[16], acc1[16];
#pragma unroll
        for (int o = 0; o < 16; o++) { acc0[o] = 0.f; acc1[o] = 0.f; }

#pragma unroll
        for (int ky = 0; ky < 8; ky++) {
            const float* ip = &img[(iy + ky) * 84 + ix];
            const float4 q0 = *(const float4*)(ip);
            const float4 q1 = *(const float4*)(ip + 4);
            const float4 q2 = *(const float4*)(ip + 8);
            float v[12];
            v[0]=q0.x; v[1]=q0.y; v[2]=q0.z; v[3]=q0.w;
            v[4]=q1.x; v[5]=q1.y; v[6]=q1.z; v[7]=q1.w;
            v[8]=q2.x; v[9]=q2.y; v[10]=q2.z; v[11]=q2.w;
#pragma unroll
            for (int kx = 0; kx < 8; kx++) {
                const float vv0 = v[kx];
                const float vv1 = v[kx + 4];
                const float* wp = &ws[(ky * 8 + kx) * 32 + ocg * 16];
                const float4 w0 = *(const float4*)(wp);
                const float4 w1 = *(const float4*)(wp + 4);
                const float4 w2 = *(const float4*)(wp + 8);
                const float4 w3 = *(const float4*)(wp + 12);
                const float wv[16] = {w0.x,w0.y,w0.z,w0.w, w1.x,w1.y,w1.z,w1.w,
                                      w2.x,w2.y,w2.z,w2.w, w3.x,w3.y,w3.z,w3.w};
#pragma unroll
                for (int o = 0; o < 16; o++) {
                    acc0[o] += vv0 * wv[o];
                    acc1[o] += vv1 * wv[o];
                }
            }
        }
        float* zp = g_z1 + (size_t)n * 12800;
#pragma unroll
        for (int o = 0; o < 16; o++) {
            const int oc = ocg * 16 + o;
            const int g = oc >> 3, l = oc & 7;
            zp[(g * 400 + p0) * 8 + l]     = fmaxf(acc0[o] + bs[oc], 0.f);
            zp[(g * 400 + p0 + 1) * 8 + l] = fmaxf(acc1[o] + bs[oc], 0.f);
        }
    }
}

// ---------------------------------------------------------------------------
// conv2: 32x20x20 -> 64x9x9, k=4, s=2. TWO images per block, 512 threads.
// Dynamic smem: in_s (2*3200) + w_s (8192) = 58368 bytes.
// ---------------------------------------------------------------------------
#define CONV2_SMEM ((2 * 3200 + 8192) * sizeof(float))
__global__ __launch_bounds__(512) void conv2_kernel(const float* __restrict__ W2,
                                                    const float* __restrict__ b2) {
    extern __shared__ float smem2[];
    float* in_s = smem2;            // [img][pix400][ic8]
    float* w_s  = smem2 + 6400;     // [oc][k16][ic8]
    const int n0 = blockIdx.x * 2;
    const int tid = threadIdx.x;
    const int img = tid >> 8;
    const int r   = tid & 255;
    const int ocg  = r & 7;
    const int trip = r >> 3;
    const bool active = (trip < 27);

    int py[3], px[3];
#pragma unroll
    for (int i = 0; i < 3; i++) {
        int p = trip * 3 + i;
        if (p > 80) p = 80;
        py[i] = p / 9; px[i] = p % 9;
    }

    float acc[3][8];
#pragma unroll
    for (int i = 0; i < 3; i++)
#pragma unroll
        for (int o = 0; o < 8; o++) acc[i][o] = 0.f;

    for (int c = 0; c < 4; c++) {
        __syncthreads();
        for (int i = tid; i < 6400; i += 512) {
            const int im2 = i / 3200, idx = i - im2 * 3200;
            in_s[i] = g_z1[((size_t)(n0 + im2) * 4 + c) * 3200 + idx];
        }
        for (int i = tid; i < 8192; i += 512) {
            int oc = i >> 7, rr = i & 127, k = rr >> 3, icl = rr & 7;
            w_s[i] = W2[oc * 512 + (c * 8 + icl) * 16 + k];
        }
        __syncthreads();
        if (active) {
            const float* inb = &in_s[img * 3200];
#pragma unroll
            for (int k = 0; k < 16; k++) {
                const int ky = k >> 2, kx = k & 3;
                float4 a[3][2];
#pragma unroll
                for (int i = 0; i < 3; i++) {
                    const int ib = ((py[i] * 2 + ky) * 20 + px[i] * 2 + kx) * 8;
                    a[i][0] = *(const float4*)&inb[ib];
                    a[i][1] = *(const float4*)&inb[ib + 4];
                }
#pragma unroll
                for (int o = 0; o < 8; o++) {
                    const float4* wp = (const float4*)&w_s[((ocg * 8 + o) * 16 + k) * 8];
                    const float4 w0 = wp[0], w1 = wp[1];
#pragma unroll
                    for (int i = 0; i < 3; i++) {
                        acc[i][o] += a[i][0].x * w0.x + a[i][0].y * w0.y +
                                     a[i][0].z * w0.z + a[i][0].w * w0.w +
                                     a[i][1].x * w1.x + a[i][1].y * w1.y +
                                     a[i][1].z * w1.z + a[i][1].w * w1.w;
                    }
                }
            }
        }
    }
    if (active) {
#pragma unroll
        for (int i = 0; i < 3; i++) {
            const int p = trip * 3 + i;
#pragma unroll
            for (int o = 0; o < 8; o++) {
                const int oc = ocg * 8 + o;
                const float v = fmaxf(acc[i][o] + b2[oc], 0.f);
                g_z2[(((size_t)(n0 + img) * 4 + (oc >> 4)) * 81 + p) * 16 + (oc & 15)] = v;
            }
        }
    }
}

// ---------------------------------------------------------------------------
// conv3: 64x9x9 -> 64x7x7, k=3, s=1. FOUR images per block, 512 threads.
// Dynamic smem: in_s (4*1296) + w_s (9216) = 57600 bytes.
// ---------------------------------------------------------------------------
#define CONV3_SMEM ((4 * 1296 + 9216) * sizeof(float))
__global__ __launch_bounds__(512) void conv3_kernel(const float* __restrict__ W3,
                                                    const float* __restrict__ b3) {
    extern __shared__ float smem3[];
    float* in_s = smem3;            // [img][pix81][ic16]
    float* w_s  = smem3 + 5184;     // [oc][k9][ic16]
    const int n0 = blockIdx.x * 4;
    const int tid = threadIdx.x;
    const int img = tid >> 7;
    const int r   = tid & 127;
    const int ty  = r / 16;     // output row 0..6
    const int og  = r % 16;     // oc group (4 oc each)
    const bool active = (r < 112);

    float acc[7][4];
#pragma unroll
    for (int i = 0; i < 7; i++)
#pragma unroll
        for (int o = 0; o < 4; o++) acc[i][o] = 0.f;

    for (int cc = 0; cc < 4; cc++) {
        __syncthreads();
        for (int i = tid; i < 5184; i += 512) {
            const int im = i / 1296, idx = i - im * 1296;
            in_s[i] = g_z2[(((size_t)(n0 + im) * 4 + cc) * 1296) + idx];
        }
        for (int i = tid; i < 9216; i += 512) {
            const int oc = i / 144, r2 = i % 144, k = r2 >> 4, icl = r2 & 15;
            w_s[i] = W3[oc * 576 + (cc * 16 + icl) * 9 + k];
        }
        __syncthreads();
        if (active) {
            const float* inb = &in_s[img * 1296];
#pragma unroll
            for (int k = 0; k < 9; k++) {
                const int ky = k / 3, kx = k % 3;
#pragma unroll
                for (int icv = 0; icv < 4; icv++) {
                    float4 av[7];
#pragma unroll
                    for (int ox = 0; ox < 7; ox++)
                        av[ox] = *(const float4*)&inb[((ty + ky) * 9 + kx + ox) * 16 + icv * 4];
#pragma unroll
                    for (int o = 0; o < 4; o++) {
                        const float4 w = *(const float4*)&w_s[((og * 4 + o) * 9 + k) * 16 + icv * 4];
#pragma unroll
                        for (int ox = 0; ox < 7; ox++) {
                            acc[ox][o] += av[ox].x * w.x + av[ox].y * w.y +
                                          av[ox].z * w.z + av[ox].w * w.w;
                        }
                    }
                }
            }
        }
    }
    if (active) {
#pragma unroll
        for (int o = 0; o < 4; o++) {
            const int oc = og * 4 + o;
            const float bb = b3[oc];
            float* zp = &g_z3[(size_t)(n0 + img) * 3136 + oc * 49 + ty * 7];
#pragma unroll
            for (int ox = 0; ox < 7; ox++)
                zp[ox] = fmaxf(acc[ox][o] + bb, 0.f);
        }
    }
}

// ---------------------------------------------------------------------------
// GEMM: C[M,N] = A[M,K] * B[N,K]^T + bias(+bias2), optional relu.
// BM=BN=64, BK=16, 256 threads, 4x4 microtile (round-1 proven version).
// ---------------------------------------------------------------------------
__device__ __forceinline__ void gemm_body(const float* __restrict__ A,
                                          const float* __restrict__ B,
                                          float* __restrict__ C, int K,
                                          const float* __restrict__ bias1,
                                          const float* __restrict__ bias2,
                                          bool relu) {
    __shared__ float As[16 * 68];
    __shared__ float Bs[16 * 68];
    const int tid = threadIdx.x;
    const int m0 = blockIdx.y * 64, n0 = blockIdx.x * 64;
    const int ar = tid >> 2, ac = (tid & 3) << 2;
    const int tx = tid & 15, ty = tid >> 4;
    const int N = 512;

    float acc[4][4];
#pragma unroll
    for (int i = 0; i < 4; i++)
#pragma unroll
        for (int j = 0; j < 4; j++) acc[i][j] = 0.f;

    const float* Ap = A + (size_t)(m0 + ar) * K + ac;
    const float* Bp = B + (size_t)(n0 + ar) * K + ac;

    for (int k0 = 0; k0 < K; k0 += 16) {
        const float4 av = *(const float4*)(Ap + k0);
        const float4 bv = *(const float4*)(Bp + k0);
        As[(ac + 0) * 68 + ar] = av.x;
        As[(ac + 1) * 68 + ar] = av.y;
        As[(ac + 2) * 68 + ar] = av.z;
        As[(ac + 3) * 68 + ar] = av.w;
        Bs[(ac + 0) * 68 + ar] = bv.x;
        Bs[(ac + 1) * 68 + ar] = bv.y;
        Bs[(ac + 2) * 68 + ar] = bv.z;
        Bs[(ac + 3) * 68 + ar] = bv.w;
        __syncthreads();
#pragma unroll
        for (int kk = 0; kk < 16; kk++) {
            const float4 a = *(const float4*)&As[kk * 68 + (ty << 2)];
            const float4 b = *(const float4*)&Bs[kk * 68 + (tx << 2)];
            acc[0][0] += a.x * b.x; acc[0][1] += a.x * b.y;
            acc[0][2] += a.x * b.z; acc[0][3] += a.x * b.w;
            acc[1][0] += a.y * b.x; acc[1][1] += a.y * b.y;
            acc[1][2] += a.y * b.z; acc[1][3] += a.y * b.w;
            acc[2][0] += a.z * b.x; acc[2][1] += a.z * b.y;
            acc[2][2] += a.z * b.z; acc[2][3] += a.z * b.w;
            acc[3][0] += a.w * b.x; acc[3][1] += a.w * b.y;
            acc[3][2] += a.w * b.z; acc[3][3] += a.w * b.w;
        }
        __syncthreads();
    }

    float bb[4];
#pragma unroll
    for (int j = 0; j < 4; j++) {
        int nn = n0 + (tx << 2) + j;
        bb[j] = bias1[nn] + (bias2 ? bias2[nn] : 0.f);
    }
#pragma unroll
    for (int i = 0; i < 4; i++) {
        float4 o;
        float v0 = acc[i][0] + bb[0], v1 = acc[i][1] + bb[1];
        float v2 = acc[i][2] + bb[2], v3 = acc[i][3] + bb[3];
        if (relu) {
            v0 = fmaxf(v0, 0.f); v1 = fmaxf(v1, 0.f);
            v2 = fmaxf(v2, 0.f); v3 = fmaxf(v3, 0.f);
        }
        o.x = v0; o.y = v1; o.z = v2; o.w = v3;
        *(float4*)&C[(size_t)(m0 + (ty << 2) + i) * N + n0 + (tx << 2)] = o;
    }
}

__global__ __launch_bounds__(256) void fc_gemm_kernel(const float* __restrict__ Wfc,
                                                      const float* __restrict__ bfc) {
    gemm_body(g_z3, Wfc, g_hidden, 3136, bfc, nullptr, true);
}
__global__ __launch_bounds__(256) void gates_gemm_kernel(const float* __restrict__ W_ih,
                                                         const float* __restrict__ b_ih,
                                                         const float* __restrict__ b_hh) {
    gemm_body(g_hidden, W_ih, g_gates, 512, b_ih, b_hh, false);
}

// ---------------------------------------------------------------------------
// W_hh transpose prep: g_whhT[k*512 + j] = W_hh[j*128 + k]
// ---------------------------------------------------------------------------
__global__ __launch_bounds__(512) void whh_transpose_kernel(const float* __restrict__ W_hh) {
    const int id = blockIdx.x * 512 + threadIdx.x;   // 0..65535
    const int k = id >> 9, j = id & 511;
    g_whhT[k * 512 + j] = W_hh[j * 128 + k];
}

// ---------------------------------------------------------------------------
// LSTM: one block per batch element, 512 threads, no grid barrier.
// thread (j4 = tid&127, ks = tid>>7): computes partial dot (k-quarter ks) of
// gate rows 4*j4..4*j4+3 via coalesced float4 loads of transposed W.
// ---------------------------------------------------------------------------
__device__ __forceinline__ float sigmoidf_(float v) {
    return 1.0f / (1.0f + __expf(-v));
}

__global__ __launch_bounds__(512) void lstm_kernel(const float* __restrict__ done,
                                                   const float* __restrict__ h0,
                                                   const float* __restrict__ c0,
                                                   float* __restrict__ out) {
    __shared__ float hm[HID];          // masked previous h
    __shared__ float cs[HID];
    __shared__ float hs[HID];
    __shared__ float part[4 * 512];    // [ks][gate row]
    const int b = blockIdx.x;
    const int tid = threadIdx.x;
    const int j4 = tid & 127;
    const int ks = tid >> 7;

    if (tid < HID) {
        hs[tid] = h0[b * HID + tid];
        cs[tid] = c0[b * HID + tid];
    }
    __syncthreads();

    for (int t = 0; t < TSTEPS; t++) {
        const float mask = 1.0f - done[t * BATCH + b];
        if (tid < HID) hm[tid] = hs[tid] * mask;
        __syncthreads();

        float a0 = 0.f, a1 = 0.f, a2 = 0.f, a3 = 0.f;
        const float4* __restrict__ wt = (const float4*)&g_whhT[(ks * 32) * 512] + j4;
        const float* __restrict__ hk = &hm[ks * 32];
#pragma unroll
        for (int kk = 0; kk < 32; kk++) {
            const float4 w = wt[kk * 128];
            const float h = hk[kk];
            a0 += w.x * h; a1 += w.y * h; a2 += w.z * h; a3 += w.w * h;
        }
        float4 pv = {a0, a1, a2, a3};
        *(float4*)&part[ks * 512 + j4 * 4] = pv;
        __syncthreads();

        // combine partials + x-projection; compute gate j = tid
        const float gx = g_gates[(size_t)(t * BATCH + b) * 512 + tid];
        const float gsum = part[tid] + part[512 + tid] + part[1024 + tid] +
                           part[1536 + tid] + gx;
        part[tid] = gsum;   // reuse as gate buffer (each thread rewrites own slot)
        __syncthreads();

        if (tid < HID) {
            const float gi = part[tid];
            const float gf = part[tid + 128];
            const float gc = part[tid + 256];
            const float go = part[tid + 384];
            float c = cs[tid] * mask;
            c = sigmoidf_(gf) * c + sigmoidf_(gi) * tanhf(gc);
            const float h = sigmoidf_(go) * tanhf(c);
            cs[tid] = c;
            hs[tid] = h;
            g_hs[(size_t)(t * BATCH + b) * HID + tid] = h;
            if (t == TSTEPS - 1) {
                out[28672 + b * HID + tid] = h;
                out[32768 + b * HID + tid] = c;
            }
        }
        __syncthreads();
    }
}

// ---------------------------------------------------------------------------
// Heads: logits (4096x6) and value (4096x1) from g_hs.
// ---------------------------------------------------------------------------
__global__ __launch_bounds__(256) void heads_kernel(const float* __restrict__ Wa,
                                                    const float* __restrict__ ba,
                                                    const float* __restrict__ Wc,
                                                    const float* __restrict__ bc,
                                                    float* __restrict__ out) {
    __shared__ float was[6 * 128];
    __shared__ float wcs[128];
    __shared__ float bas[6];
    __shared__ float bcs;
    const int tid = threadIdx.x;
    for (int i = tid; i < 768; i += 256) was[i] = Wa[i];
    if (tid < 128) wcs[tid] = Wc[tid];
    if (tid < 6) bas[tid] = ba[tid];
    if (tid == 0) bcs = bc[0];
    __syncthreads();

    const int row = blockIdx.x * 256 + tid;
    const float* hp = &g_hs[(size_t)row * 128];
    float acc[6] = {0.f, 0.f, 0.f, 0.f, 0.f, 0.f};
    float accv = 0.f;
    for (int k = 0; k < 128; k += 4) {
        const float4 h4 = *(const float4*)&hp[k];
#pragma unroll
        for (int a = 0; a < 6; a++) {
            const float4 w4 = *(const float4*)&was[a * 128 + k];
            acc[a] += h4.x * w4.x + h4.y * w4.y + h4.z * w4.z + h4.w * w4.w;
        }
        const float4 wc4 = *(const float4*)&wcs[k];
        accv += h4.x * wc4.x + h4.y * wc4.y + h4.z * wc4.z + h4.w * wc4.w;
    }
#pragma unroll
    for (int a = 0; a < 6; a++) out[row * 6 + a] = acc[a] + bas[a];
    out[24576 + row] = accv + bcs;
}

// ---------------------------------------------------------------------------
// Launch
// ---------------------------------------------------------------------------
extern "C" void kernel_launch(void* const* d_in, const int* in_sizes, int n_in,
                              void* d_out, int out_size) {
    const float* x    = (const float*)d_in[0];
    const float* done = (const float*)d_in[1];
    const float* h0   = (const float*)d_in[2];
    const float* c0   = (const float*)d_in[3];
    const float* W1   = (const float*)d_in[4];
    const float* b1   = (const float*)d_in[5];
    const float* W2   = (const float*)d_in[6];
    const float* b2   = (const float*)d_in[7];
    const float* W3   = (const float*)d_in[8];
    const float* b3   = (const float*)d_in[9];
    const float* Wfc  = (const float*)d_in[10];
    const float* bfc  = (const float*)d_in[11];
    const float* W_ih = (const float*)d_in[12];
    const float* W_hh = (const float*)d_in[13];
    const float* b_ih = (const float*)d_in[14];
    const float* b_hh = (const float*)d_in[15];
    const float* Wa   = (const float*)d_in[16];
    const float* ba   = (const float*)d_in[17];
    const float* Wc   = (const float*)d_in[18];
    const float* bc   = (const float*)d_in[19];
    float* out = (float*)d_out;

    // Opt in to >48KB dynamic smem (host-side attribute; not a stream op,
    // not an allocation — safe under graph capture, idempotent).
    static bool attr_done = false;
    if (!attr_done) {
        cudaFuncSetAttribute(conv2_kernel,
                             cudaFuncAttributeMaxDynamicSharedMemorySize,
                             (int)CONV2_SMEM);
        cudaFuncSetAttribute(conv3_kernel,
                             cudaFuncAttributeMaxDynamicSharedMemorySize,
                             (int)CONV3_SMEM);
        attr_done = true;
    }

    whh_transpose_kernel<<<128, 512>>>(W_hh);
    conv1_kernel<<<NIMG, 512>>>(x, W1, b1);
    conv2_kernel<<<NIMG / 2, 512, CONV2_SMEM>>>(W2, b2);
    conv3_kernel<<<NIMG / 4, 512, CONV3_SMEM>>>(W3, b3);
    fc_gemm_kernel<<<dim3(8, 64), 256>>>(Wfc, bfc);
    gates_gemm_kernel<<<dim3(8, 64), 256>>>(W_ih, b_ih, b_hh);
    lstm_kernel<<<BATCH, 512>>>(done, h0, c0, out);
    heads_kernel<<<16, 256>>>(Wa, ba, Wc, bc, out);
}

// round 5
// speedup vs baseline: 1.4978x; 1.3095x over previous
#include <cuda_runtime.h>
#include <cstdint>

#define NIMG   4096
#define TSTEPS 128
#define BATCH  32
#define HID    128

// Scratch (device globals; no allocation allowed)
__device__ float g_z1[(size_t)NIMG * 4 * 400 * 8];    // conv1 out [n][g=oc/8][pix400][oc%8]
__device__ float g_z2[(size_t)NIMG * 4 * 81 * 16];    // conv2 out [n][cc=oc/16][pix81][oc%16]
__device__ float g_z3[(size_t)NIMG * 3136];           // conv3 out, NCHW flatten
__device__ float g_hidden[(size_t)NIMG * 512];        // FC out
__device__ float g_gates[(size_t)NIMG * 512];         // x-proj of gates (+both biases)
__device__ float g_hs[(size_t)NIMG * HID];            // per-step hidden outputs
__device__ float g_whhT[HID * 512];                   // W_hh transposed: [k][row j]

// ---------------------------------------------------------------------------
// conv1: 1x84x84 -> 32x20x20, k=8, s=4. One block per image. (round-1 proven)
// ---------------------------------------------------------------------------
__global__ __launch_bounds__(512) void conv1_kernel(const float* __restrict__ x,
                                                    const float* __restrict__ W1,
                                                    const float* __restrict__ b1) {
    __shared__ float img[84 * 84];
    __shared__ float ws[64 * 32];   // [k][oc]
    __shared__ float bs[32];
    const int n = blockIdx.x;
    const int tid = threadIdx.x;
    const float* xin = x + (size_t)n * 7056;
    for (int i = tid; i < 7056; i += 512) img[i] = xin[i] * (1.0f / 255.0f);
    for (int i = tid; i < 2048; i += 512) {
        int k = i >> 5, oc = i & 31;
        ws[i] = W1[oc * 64 + k];
    }
    if (tid < 32) bs[tid] = b1[tid];
    __syncthreads();

    if (tid < 400) {
        const int oy = tid / 20, ox = tid % 20;
        const int iy = oy * 4, ix = ox * 4;
        float acc[32];
#pragma unroll
        for (int o = 0; o < 32; o++) acc[o] = 0.f;
#pragma unroll
        for (int ky = 0; ky < 8; ky++) {
            const float* ip = &img[(iy + ky) * 84 + ix];
            float v[8];
#pragma unroll
            for (int kx = 0; kx < 8; kx++) v[kx] = ip[kx];
#pragma unroll
            for (int kx = 0; kx < 8; kx++) {
                const float* wp = &ws[(ky * 8 + kx) * 32];
                float vv = v[kx];
#pragma unroll
                for (int o = 0; o < 32; o++) acc[o] += vv * wp[o];
            }
        }
        float* zp = g_z1 + (size_t)n * 12800;
#pragma unroll
        for (int o = 0; o < 32; o++) {
            float r = fmaxf(acc[o] + bs[o], 0.f);
            int g = o >> 3, l = o & 7;
            zp[(g * 400 + tid) * 8 + l] = r;
        }
    }
}

// ---------------------------------------------------------------------------
// conv2: 32x20x20 -> 64x9x9, k=4, s=2. One block per image. (round-1 proven)
// ---------------------------------------------------------------------------
__global__ __launch_bounds__(672) void conv2_kernel(const float* __restrict__ W2,
                                                    const float* __restrict__ b2) {
    __shared__ float in_s[400 * 8];     // [pix][ic8]
    __shared__ float w_s[64 * 16 * 8];  // [oc][k16][ic8]
    const int n = blockIdx.x;
    const int tid = threadIdx.x;
    const int ocg = tid / 81, p = tid % 81;
    const int oy = p / 9, ox = p % 9;
    const bool active = (tid < 648);
    float acc[8];
#pragma unroll
    for (int o = 0; o < 8; o++) acc[o] = 0.f;

    for (int c = 0; c < 4; c++) {
        __syncthreads();
        const float* zin = g_z1 + ((size_t)n * 4 + c) * 3200;
        for (int i = tid; i < 3200; i += blockDim.x) in_s[i] = zin[i];
        for (int i = tid; i < 8192; i += blockDim.x) {
            int oc = i >> 7, r = i & 127, k = r >> 3, icl = r & 7;
            w_s[i] = W2[oc * 512 + (c * 8 + icl) * 16 + k];
        }
        __syncthreads();
        if (active) {
#pragma unroll
            for (int k = 0; k < 16; k++) {
                const int ky = k >> 2, kx = k & 3;
                const float4* ip =
                    (const float4*)&in_s[((oy * 2 + ky) * 20 + (ox * 2 + kx)) * 8];
                const float4 a0 = ip[0], a1 = ip[1];
#pragma unroll
                for (int o = 0; o < 8; o++) {
                    const float4* wp = (const float4*)&w_s[((ocg * 8 + o) * 16 + k) * 8];
                    const float4 w0 = wp[0], w1 = wp[1];
                    acc[o] += a0.x * w0.x + a0.y * w0.y + a0.z * w0.z + a0.w * w0.w +
                              a1.x * w1.x + a1.y * w1.y + a1.z * w1.z + a1.w * w1.w;
                }
            }
        }
    }
    if (active) {
#pragma unroll
        for (int o = 0; o < 8; o++) {
            int oc = ocg * 8 + o;
            float r = fmaxf(acc[o] + b2[oc], 0.f);
            g_z2[(((size_t)n * 4 + (oc >> 4)) * 81 + p) * 16 + (oc & 15)] = r;
        }
    }
}

// ---------------------------------------------------------------------------
// conv3: 64x9x9 -> 64x7x7, k=3, s=1. One block per image. (round-1 proven)
// ---------------------------------------------------------------------------
__global__ __launch_bounds__(416) void conv3_kernel(const float* __restrict__ W3,
                                                    const float* __restrict__ b3) {
    __shared__ float in_s[81 * 16];     // [pix][ic16]
    __shared__ float w_s[64 * 9 * 16];  // [oc][k9][ic16]
    const int n = blockIdx.x;
    const int tid = threadIdx.x;
    const int ocg = tid / 49, p = tid % 49;
    const int oy = p / 7, ox = p % 7;
    const bool active = (tid < 392);
    float acc[8];
#pragma unroll
    for (int o = 0; o < 8; o++) acc[o] = 0.f;

    for (int cc = 0; cc < 4; cc++) {
        __syncthreads();
        const float* zin = g_z2 + ((size_t)n * 4 + cc) * 1296;
        for (int i = tid; i < 1296; i += blockDim.x) in_s[i] = zin[i];
        for (int i = tid; i < 9216; i += blockDim.x) {
            int oc = i / 144, r = i % 144, k = r >> 4, icl = r & 15;
            w_s[i] = W3[oc * 576 + (cc * 16 + icl) * 9 + k];
        }
        __syncthreads();
        if (active) {
#pragma unroll
            for (int k = 0; k < 9; k++) {
                const int ky = k / 3, kx = k % 3;
                const float4* ip = (const float4*)&in_s[((oy + ky) * 9 + (ox + kx)) * 16];
                const float4 a0 = ip[0], a1 = ip[1], a2 = ip[2], a3 = ip[3];
#pragma unroll
                for (int o = 0; o < 8; o++) {
                    const float4* wp = (const float4*)&w_s[((ocg * 8 + o) * 9 + k) * 16];
                    const float4 w0 = wp[0], w1 = wp[1], w2 = wp[2], w3 = wp[3];
                    acc[o] += a0.x * w0.x + a0.y * w0.y + a0.z * w0.z + a0.w * w0.w +
                              a1.x * w1.x + a1.y * w1.y + a1.z * w1.z + a1.w * w1.w +
                              a2.x * w2.x + a2.y * w2.y + a2.z * w2.z + a2.w * w2.w +
                              a3.x * w3.x + a3.y * w3.y + a3.z * w3.z + a3.w * w3.w;
                }
            }
        }
    }
    if (active) {
#pragma unroll
        for (int o = 0; o < 8; o++) {
            int oc = ocg * 8 + o;
            float r = fmaxf(acc[o] + b3[oc], 0.f);
            g_z3[(size_t)n * 3136 + oc * 49 + p] = r;
        }
    }
}

// ---------------------------------------------------------------------------
// GEMM: C[M,N] = A[M,K] * B[N,K]^T + bias(+bias2), optional relu.
// BM=BN=64, BK=16, 256 threads, 4x4 microtile (round-1 proven).
// ---------------------------------------------------------------------------
__device__ __forceinline__ void gemm_body(const float* __restrict__ A,
                                          const float* __restrict__ B,
                                          float* __restrict__ C, int K,
                                          const float* __restrict__ bias1,
                                          const float* __restrict__ bias2,
                                          bool relu) {
    __shared__ float As[16 * 68];
    __shared__ float Bs[16 * 68];
    const int tid = threadIdx.x;
    const int m0 = blockIdx.y * 64, n0 = blockIdx.x * 64;
    const int ar = tid >> 2, ac = (tid & 3) << 2;
    const int tx = tid & 15, ty = tid >> 4;
    const int N = 512;

    float acc[4][4];
#pragma unroll
    for (int i = 0; i < 4; i++)
#pragma unroll
        for (int j = 0; j < 4; j++) acc[i][j] = 0.f;

    const float* Ap = A + (size_t)(m0 + ar) * K + ac;
    const float* Bp = B + (size_t)(n0 + ar) * K + ac;

    for (int k0 = 0; k0 < K; k0 += 16) {
        const float4 av = *(const float4*)(Ap + k0);
        const float4 bv = *(const float4*)(Bp + k0);
        As[(ac + 0) * 68 + ar] = av.x;
        As[(ac + 1) * 68 + ar] = av.y;
        As[(ac + 2) * 68 + ar] = av.z;
        As[(ac + 3) * 68 + ar] = av.w;
        Bs[(ac + 0) * 68 + ar] = bv.x;
        Bs[(ac + 1) * 68 + ar] = bv.y;
        Bs[(ac + 2) * 68 + ar] = bv.z;
        Bs[(ac + 3) * 68 + ar] = bv.w;
        __syncthreads();
#pragma unroll
        for (int kk = 0; kk < 16; kk++) {
            const float4 a = *(const float4*)&As[kk * 68 + (ty << 2)];
            const float4 b = *(const float4*)&Bs[kk * 68 + (tx << 2)];
            acc[0][0] += a.x * b.x; acc[0][1] += a.x * b.y;
            acc[0][2] += a.x * b.z; acc[0][3] += a.x * b.w;
            acc[1][0] += a.y * b.x; acc[1][1] += a.y * b.y;
            acc[1][2] += a.y * b.z; acc[1][3] += a.y * b.w;
            acc[2][0] += a.z * b.x; acc[2][1] += a.z * b.y;
            acc[2][2] += a.z * b.z; acc[2][3] += a.z * b.w;
            acc[3][0] += a.w * b.x; acc[3][1] += a.w * b.y;
            acc[3][2] += a.w * b.z; acc[3][3] += a.w * b.w;
        }
        __syncthreads();
    }

    float bb[4];
#pragma unroll
    for (int j = 0; j < 4; j++) {
        int nn = n0 + (tx << 2) + j;
        bb[j] = bias1[nn] + (bias2 ? bias2[nn] : 0.f);
    }
#pragma unroll
    for (int i = 0; i < 4; i++) {
        float4 o;
        float v0 = acc[i][0] + bb[0], v1 = acc[i][1] + bb[1];
        float v2 = acc[i][2] + bb[2], v3 = acc[i][3] + bb[3];
        if (relu) {
            v0 = fmaxf(v0, 0.f); v1 = fmaxf(v1, 0.f);
            v2 = fmaxf(v2, 0.f); v3 = fmaxf(v3, 0.f);
        }
        o.x = v0; o.y = v1; o.z = v2; o.w = v3;
        *(float4*)&C[(size_t)(m0 + (ty << 2) + i) * N + n0 + (tx << 2)] = o;
    }
}

__global__ __launch_bounds__(256) void fc_gemm_kernel(const float* __restrict__ Wfc,
                                                      const float* __restrict__ bfc) {
    gemm_body(g_z3, Wfc, g_hidden, 3136, bfc, nullptr, true);
}
__global__ __launch_bounds__(256) void gates_gemm_kernel(const float* __restrict__ W_ih,
                                                         const float* __restrict__ b_ih,
                                                         const float* __restrict__ b_hh) {
    gemm_body(g_hidden, W_ih, g_gates, 512, b_ih, b_hh, false);
}

// ---------------------------------------------------------------------------
// W_hh transpose prep: g_whhT[k*512 + j] = W_hh[j*128 + k]
// ---------------------------------------------------------------------------
__global__ __launch_bounds__(512) void whh_transpose_kernel(const float* __restrict__ W_hh) {
    const int id = blockIdx.x * 512 + threadIdx.x;   // 0..65535
    const int k = id >> 9, j = id & 511;
    g_whhT[k * 512 + j] = W_hh[j * 128 + k];
}

// ---------------------------------------------------------------------------
// LSTM: one block per batch element, 512 threads, no grid barrier.
// (round-4 proven coalesced version)
// ---------------------------------------------------------------------------
__device__ __forceinline__ float sigmoidf_(float v) {
    return 1.0f / (1.0f + __expf(-v));
}

__global__ __launch_bounds__(512) void lstm_kernel(const float* __restrict__ done,
                                                   const float* __restrict__ h0,
                                                   const float* __restrict__ c0,
                                                   float* __restrict__ out) {
    __shared__ float hm[HID];          // masked previous h
    __shared__ float cs[HID];
    __shared__ float hs[HID];
    __shared__ float part[4 * 512];    // [ks][gate row]
    const int b = blockIdx.x;
    const int tid = threadIdx.x;
    const int j4 = tid & 127;
    const int ks = tid >> 7;

    if (tid < HID) {
        hs[tid] = h0[b * HID + tid];
        cs[tid] = c0[b * HID + tid];
    }
    __syncthreads();

    for (int t = 0; t < TSTEPS; t++) {
        const float mask = 1.0f - done[t * BATCH + b];
        if (tid < HID) hm[tid] = hs[tid] * mask;
        __syncthreads();

        float a0 = 0.f, a1 = 0.f, a2 = 0.f, a3 = 0.f;
        const float4* __restrict__ wt = (const float4*)&g_whhT[(ks * 32) * 512] + j4;
        const float* __restrict__ hk = &hm[ks * 32];
#pragma unroll
        for (int kk = 0; kk < 32; kk++) {
            const float4 w = wt[kk * 128];
            const float h = hk[kk];
            a0 += w.x * h; a1 += w.y * h; a2 += w.z * h; a3 += w.w * h;
        }
        float4 pv = {a0, a1, a2, a3};
        *(float4*)&part[ks * 512 + j4 * 4] = pv;
        __syncthreads();

        // combine partials + x-projection; compute gate j = tid
        const float gx = g_gates[(size_t)(t * BATCH + b) * 512 + tid];
        const float gsum = part[tid] + part[512 + tid] + part[1024 + tid] +
                           part[1536 + tid] + gx;
        part[tid] = gsum;   // reuse as gate buffer (each thread rewrites own slot)
        __syncthreads();

        if (tid < HID) {
            const float gi = part[tid];
            const float gf = part[tid + 128];
            const float gc = part[tid + 256];
            const float go = part[tid + 384];
            float c = cs[tid] * mask;
            c = sigmoidf_(gf) * c + sigmoidf_(gi) * tanhf(gc);
            const float h = sigmoidf_(go) * tanhf(c);
            cs[tid] = c;
            hs[tid] = h;
            g_hs[(size_t)(t * BATCH + b) * HID + tid] = h;
            if (t == TSTEPS - 1) {
                out[28672 + b * HID + tid] = h;
                out[32768 + b * HID + tid] = c;
            }
        }
        __syncthreads();
    }
}

// ---------------------------------------------------------------------------
// Heads: logits (4096x6) and value (4096x1) from g_hs.
// ---------------------------------------------------------------------------
__global__ __launch_bounds__(256) void heads_kernel(const float* __restrict__ Wa,
                                                    const float* __restrict__ ba,
                                                    const float* __restrict__ Wc,
                                                    const float* __restrict__ bc,
                                                    float* __restrict__ out) {
    __shared__ float was[6 * 128];
    __shared__ float wcs[128];
    __shared__ float bas[6];
    __shared__ float bcs;
    const int tid = threadIdx.x;
    for (int i = tid; i < 768; i += 256) was[i] = Wa[i];
    if (tid < 128) wcs[tid] = Wc[tid];
    if (tid < 6) bas[tid] = ba[tid];
    if (tid == 0) bcs = bc[0];
    __syncthreads();

    const int row = blockIdx.x * 256 + tid;
    const float* hp = &g_hs[(size_t)row * 128];
    float acc[6] = {0.f, 0.f, 0.f, 0.f, 0.f, 0.f};
    float accv = 0.f;
    for (int k = 0; k < 128; k += 4) {
        const float4 h4 = *(const float4*)&hp[k];
#pragma unroll
        for (int a = 0; a < 6; a++) {
            const float4 w4 = *(const float4*)&was[a * 128 + k];
            acc[a] += h4.x * w4.x + h4.y * w4.y + h4.z * w4.z + h4.w * w4.w;
        }
        const float4 wc4 = *(const float4*)&wcs[k];
        accv += h4.x * wc4.x + h4.y * wc4.y + h4.z * wc4.z + h4.w * wc4.w;
    }
#pragma unroll
    for (int a = 0; a < 6; a++) out[row * 6 + a] = acc[a] + bas[a];
    out[24576 + row] = accv + bcs;
}

// ---------------------------------------------------------------------------
// Launch
// ---------------------------------------------------------------------------
extern "C" void kernel_launch(void* const* d_in, const int* in_sizes, int n_in,
                              void* d_out, int out_size) {
    const float* x    = (const float*)d_in[0];
    const float* done = (const float*)d_in[1];
    const float* h0   = (const float*)d_in[2];
    const float* c0   = (const float*)d_in[3];
    const float* W1   = (const float*)d_in[4];
    const float* b1   = (const float*)d_in[5];
    const float* W2   = (const float*)d_in[6];
    const float* b2   = (const float*)d_in[7];
    const float* W3   = (const float*)d_in[8];
    const float* b3   = (const float*)d_in[9];
    const float* Wfc  = (const float*)d_in[10];
    const float* bfc  = (const float*)d_in[11];
    const float* W_ih = (const float*)d_in[12];
    const float* W_hh = (const float*)d_in[13];
    const float* b_ih = (const float*)d_in[14];
    const float* b_hh = (const float*)d_in[15];
    const float* Wa   = (const float*)d_in[16];
    const float* ba   = (const float*)d_in[17];
    const float* Wc   = (const float*)d_in[18];
    const float* bc   = (const float*)d_in[19];
    float* out = (float*)d_out;

    whh_transpose_kernel<<<128, 512>>>(W_hh);
    conv1_kernel<<<NIMG, 512>>>(x, W1, b1);
    conv2_kernel<<<NIMG, 672>>>(W2, b2);
    conv3_kernel<<<NIMG, 416>>>(W3, b3);
    fc_gemm_kernel<<<dim3(8, 64), 256>>>(Wfc, bfc);
    gates_gemm_kernel<<<dim3(8, 64), 256>>>(W_ih, b_ih, b_hh);
    lstm_kernel<<<BATCH, 512>>>(done, h0, c0, out);
    heads_kernel<<<16, 256>>>(Wa, ba, Wc, bc, out);
}